// round 2
// baseline (speedup 1.0000x reference)
#include <cuda_runtime.h>
#include <math.h>
#include <stdint.h>

#define DIMS   2560
#define NH     32
#define HD     80
#define SEQ    2048
#define QKV_N  (3*DIMS)

// ---------------- scratch (static device globals; no runtime allocation) ----
__device__ float g_qkv [SEQ * QKV_N];   // [t][3*DIMS]  q|k|v
__device__ float g_attn[SEQ * DIMS];    // attention output, pre out-proj

// ============================================================================
// GEMM: C[M,N] = A[M,K] @ B[N,K]^T + bias[N]
// 128x128 block tile, BK=16, 256 threads, 8x8 microtile.
// All dims here are exact multiples (M=2048, N in {7680,2560}, K=2560).
// ============================================================================
#define BM 128
#define BN 128
#define BK 16

__global__ __launch_bounds__(256) void gemm_tn_bias(
    const float* __restrict__ A,
    const float* __restrict__ B,
    const float* __restrict__ bias,
    float* __restrict__ C,
    int M, int N, int K)
{
    __shared__ float As[BK][BM + 4];
    __shared__ float Bs[BK][BN + 4];

    const int bm  = blockIdx.y * BM;
    const int bn  = blockIdx.x * BN;
    const int tid = threadIdx.x;
    const int tx  = tid & 15;
    const int ty  = tid >> 4;

    float acc[8][8];
#pragma unroll
    for (int i = 0; i < 8; i++)
#pragma unroll
        for (int j = 0; j < 8; j++) acc[i][j] = 0.f;

    const int lr = tid >> 2;          // 0..63
    const int lc = (tid & 3) << 2;    // 0,4,8,12

    const float* Aptr = A + (size_t)(bm + lr) * K + lc;
    const float* Bptr = B + (size_t)(bn + lr) * K + lc;

    for (int k0 = 0; k0 < K; k0 += BK) {
#pragma unroll
        for (int i = 0; i < 2; i++) {
            float4 v = *(const float4*)(Aptr + (size_t)i * 64 * K + k0);
            int r = lr + i * 64;
            As[lc + 0][r] = v.x; As[lc + 1][r] = v.y;
            As[lc + 2][r] = v.z; As[lc + 3][r] = v.w;
        }
#pragma unroll
        for (int i = 0; i < 2; i++) {
            float4 v = *(const float4*)(Bptr + (size_t)i * 64 * K + k0);
            int r = lr + i * 64;
            Bs[lc + 0][r] = v.x; Bs[lc + 1][r] = v.y;
            Bs[lc + 2][r] = v.z; Bs[lc + 3][r] = v.w;
        }
        __syncthreads();

#pragma unroll
        for (int k = 0; k < BK; k++) {
            float a[8], b[8];
            *(float4*)&a[0] = *(const float4*)&As[k][ty * 8 + 0];
            *(float4*)&a[4] = *(const float4*)&As[k][ty * 8 + 4];
            *(float4*)&b[0] = *(const float4*)&Bs[k][tx * 8 + 0];
            *(float4*)&b[4] = *(const float4*)&Bs[k][tx * 8 + 4];
#pragma unroll
            for (int i = 0; i < 8; i++)
#pragma unroll
                for (int j = 0; j < 8; j++)
                    acc[i][j] = fmaf(a[i], b[j], acc[i][j]);
        }
        __syncthreads();
    }

#pragma unroll
    for (int i = 0; i < 8; i++) {
        const int row = bm + ty * 8 + i;
#pragma unroll
        for (int j = 0; j < 8; j += 4) {
            const int col = bn + tx * 8 + j;
            float4 o;
            o.x = acc[i][j + 0] + bias[col + 0];
            o.y = acc[i][j + 1] + bias[col + 1];
            o.z = acc[i][j + 2] + bias[col + 2];
            o.w = acc[i][j + 3] + bias[col + 3];
            *(float4*)&C[(size_t)row * N + col] = o;
        }
    }
}

// ============================================================================
// RoPE on q and k (first 32 dims of each 80-dim head), in place.
// pair (d, d+16), d in [0,16), theta = t * base^(-d/16)
// ============================================================================
__global__ void rope_kernel(float* __restrict__ qkv)
{
    int idx = blockIdx.x * blockDim.x + threadIdx.x;      // SEQ*NH*16 total
    if (idx >= SEQ * NH * 16) return;
    const int d = idx & 15;
    const int h = (idx >> 4) & 31;
    const int t = idx >> 9;

    const float freq  = __expf(-(float)d * 0.5756462732485115f); // ln(1e4)/16
    const float theta = (float)t * freq;
    float s, c;
    sincosf(theta, &s, &c);

    size_t base = (size_t)t * QKV_N + h * HD;
    // q
    {
        float x1 = qkv[base + d], x2 = qkv[base + d + 16];
        qkv[base + d]      = x1 * c - x2 * s;
        qkv[base + d + 16] = x1 * s + x2 * c;
    }
    // k
    base += DIMS;
    {
        float x1 = qkv[base + d], x2 = qkv[base + d + 16];
        qkv[base + d]      = x1 * c - x2 * s;
        qkv[base + d + 16] = x1 * s + x2 * c;
    }
}

// ============================================================================
// Flash attention, fp32, causal. One block = (head, 64-query tile).
// Dynamic smem layout (floats):
//   Qs [80][64]        off 0      (Q transposed: [d][row])
//   Ks [80][64]        off 5120
//   Vs [64][88]        off 10240  (row-major, padded stride 88)
//   Ps [64][68]        off 15872  (scores/probs transposed: [key][row], pad 68)
//   red[64][4]         off 20224
//   mrow[64]           off 20480
//   lrow[64]           off 20544
//   arow[64]           off 20608
// total 20672 floats = 82688 bytes
// ============================================================================
#define QS_OFF   0
#define KS_OFF   5120
#define VS_OFF   10240
#define PS_OFF   15872
#define RED_OFF  20224
#define M_OFF    20480
#define L_OFF    20544
#define AL_OFF   20608
#define ATT_SMEM_BYTES (20672 * 4)

__global__ __launch_bounds__(256) void attn_kernel(
    const float* __restrict__ qkv, float* __restrict__ out)
{
    extern __shared__ float sm[];
    float* Qs   = sm + QS_OFF;
    float* Ks   = sm + KS_OFF;
    float* Vs   = sm + VS_OFF;
    float* Ps   = sm + PS_OFF;
    float* red  = sm + RED_OFF;
    float* mrow = sm + M_OFF;
    float* lrow = sm + L_OFF;
    float* arow = sm + AL_OFF;

    const int h   = blockIdx.x;
    const int qb  = blockIdx.y;
    const int tid = threadIdx.x;
    const int q0  = qb * 64;

    // ---- load Q tile transposed: Qs[d][r] ----
    {
        const int r  = tid >> 2;
        const int dq = (tid & 3) * 20;
        const float* src = qkv + (size_t)(q0 + r) * QKV_N + h * HD + dq;
#pragma unroll
        for (int u = 0; u < 5; u++) {
            float4 v = *(const float4*)(src + u * 4);
            const int d = dq + u * 4;
            Qs[(d + 0) * 64 + r] = v.x; Qs[(d + 1) * 64 + r] = v.y;
            Qs[(d + 2) * 64 + r] = v.z; Qs[(d + 3) * 64 + r] = v.w;
        }
    }

    const int pr = (tid >> 4) * 4;   // PV row base
    const int pd = (tid & 15) * 5;   // PV d base
    float o[4][5];
#pragma unroll
    for (int i = 0; i < 4; i++)
#pragma unroll
        for (int j = 0; j < 5; j++) o[i][j] = 0.f;

    if (tid < 64) { mrow[tid] = -3.0e38f; lrow[tid] = 0.f; }
    __syncthreads();

    const float scale = 0.11180339887498949f;   // 1/sqrt(80)
    const int ntiles = qb + 1;

    for (int kb = 0; kb < ntiles; kb++) {
        const int k0 = kb * 64;

        // ---- load K tile transposed + V tile ----
        {
            const int r  = tid >> 2;
            const int dq = (tid & 3) * 20;
            const float* ksrc = qkv + DIMS   + (size_t)(k0 + r) * QKV_N + h * HD + dq;
            const float* vsrc = qkv + 2*DIMS + (size_t)(k0 + r) * QKV_N + h * HD + dq;
#pragma unroll
            for (int u = 0; u < 5; u++) {
                float4 v = *(const float4*)(ksrc + u * 4);
                const int d = dq + u * 4;
                Ks[(d + 0) * 64 + r] = v.x; Ks[(d + 1) * 64 + r] = v.y;
                Ks[(d + 2) * 64 + r] = v.z; Ks[(d + 3) * 64 + r] = v.w;
            }
#pragma unroll
            for (int u = 0; u < 5; u++) {
                *(float4*)&Vs[r * 88 + dq + u * 4] = *(const float4*)(vsrc + u * 4);
            }
        }
        __syncthreads();

        // ---- S = Q K^T (4x4 microtile per thread) ----
        const int sx = (tid & 15) * 4;   // key cols
        const int sy = (tid >> 4) * 4;   // q rows
        float s[4][4];
#pragma unroll
        for (int i = 0; i < 4; i++)
#pragma unroll
            for (int j = 0; j < 4; j++) s[i][j] = 0.f;

#pragma unroll 4
        for (int d = 0; d < HD; d++) {
            float4 qv = *(const float4*)&Qs[d * 64 + sy];
            float4 kv = *(const float4*)&Ks[d * 64 + sx];
            float qa[4] = {qv.x, qv.y, qv.z, qv.w};
            float ka[4] = {kv.x, kv.y, kv.z, kv.w};
#pragma unroll
            for (int i = 0; i < 4; i++)
#pragma unroll
                for (int j = 0; j < 4; j++)
                    s[i][j] = fmaf(qa[i], ka[j], s[i][j]);
        }

        // write transposed (masked + scaled): Ps[key][row]
#pragma unroll
        for (int j = 0; j < 4; j++) {
            const int gcol = k0 + sx + j;
#pragma unroll
            for (int i = 0; i < 4; i++) {
                const int grow = q0 + sy + i;
                float val = (gcol <= grow) ? s[i][j] * scale : -1.0e30f;
                Ps[(sx + j) * 68 + (sy + i)] = val;
            }
        }
        __syncthreads();

        // ---- online softmax ----
        {   // partial row max
            const int r = tid >> 2, seg = tid & 3;
            float mx = -3.0e38f;
            const int c0 = seg * 16;
#pragma unroll
            for (int c = 0; c < 16; c++) mx = fmaxf(mx, Ps[(c0 + c) * 68 + r]);
            red[r * 4 + seg] = mx;
        }
        __syncthreads();
        if (tid < 64) {
            float mt = fmaxf(fmaxf(red[tid*4+0], red[tid*4+1]),
                             fmaxf(red[tid*4+2], red[tid*4+3]));
            float mo = mrow[tid];
            float mn = fmaxf(mo, mt);
            float al = __expf(mo - mn);
            mrow[tid] = mn; arow[tid] = al; lrow[tid] *= al;
        }
        __syncthreads();
        {   // exponentiate + partial sums
            const int r = tid >> 2, seg = tid & 3;
            const float mn = mrow[r];
            const int c0 = seg * 16;
            float ss = 0.f;
#pragma unroll
            for (int c = 0; c < 16; c++) {
                float e = __expf(Ps[(c0 + c) * 68 + r] - mn);
                Ps[(c0 + c) * 68 + r] = e;
                ss += e;
            }
            red[r * 4 + seg] = ss;
        }
        __syncthreads();
        if (tid < 64)
            lrow[tid] += red[tid*4+0] + red[tid*4+1] + red[tid*4+2] + red[tid*4+3];

        // ---- rescale O, accumulate P V ----
        float al[4];
#pragma unroll
        for (int i = 0; i < 4; i++) al[i] = arow[pr + i];
#pragma unroll
        for (int i = 0; i < 4; i++)
#pragma unroll
            for (int j = 0; j < 5; j++) o[i][j] *= al[i];

#pragma unroll 4
        for (int c = 0; c < 64; c++) {
            float4 p4 = *(const float4*)&Ps[c * 68 + pr];
            float pv[4] = {p4.x, p4.y, p4.z, p4.w};
#pragma unroll
            for (int j = 0; j < 5; j++) {
                float v = Vs[c * 88 + pd + j];
#pragma unroll
                for (int i = 0; i < 4; i++)
                    o[i][j] = fmaf(pv[i], v, o[i][j]);
            }
        }
        __syncthreads();   // protect Ks/Vs/Ps for next tile; also orders lrow
    }

    // ---- epilogue ----
    float inv[4];
#pragma unroll
    for (int i = 0; i < 4; i++) inv[i] = 1.f / lrow[pr + i];
#pragma unroll
    for (int i = 0; i < 4; i++) {
        const int row = q0 + pr + i;
#pragma unroll
        for (int j = 0; j < 5; j++)
            out[(size_t)row * DIMS + h * HD + pd + j] = o[i][j] * inv[i];
    }
}

// ============================================================================
extern "C" void kernel_launch(void* const* d_in, const int* in_sizes, int n_in,
                              void* d_out, int out_size)
{
    const float* x       = (const float*)d_in[0];
    const float* Wqkv_w  = (const float*)d_in[1];
    const float* Wqkv_b  = (const float*)d_in[2];
    const float* out_w   = (const float*)d_in[3];
    const float* out_b   = (const float*)d_in[4];
    // d_in[5] = mask: causal triu(-1e9), implemented structurally; unused.
    float* outp = (float*)d_out;

    float *qkv_ptr = nullptr, *attn_ptr = nullptr;
    cudaGetSymbolAddress((void**)&qkv_ptr,  g_qkv);
    cudaGetSymbolAddress((void**)&attn_ptr, g_attn);

    cudaFuncSetAttribute(attn_kernel,
                         cudaFuncAttributeMaxDynamicSharedMemorySize,
                         ATT_SMEM_BYTES);

    // 1) QKV projection
    {
        dim3 grid(QKV_N / BN, SEQ / BM);
        gemm_tn_bias<<<grid, 256>>>(x, Wqkv_w, Wqkv_b, qkv_ptr, SEQ, QKV_N, DIMS);
    }
    // 2) RoPE on q,k
    {
        int total = SEQ * NH * 16;
        rope_kernel<<<(total + 255) / 256, 256>>>(qkv_ptr);
    }
    // 3) causal flash attention
    {
        dim3 grid(NH, SEQ / 64);
        attn_kernel<<<grid, 256, ATT_SMEM_BYTES>>>(qkv_ptr, attn_ptr);
    }
    // 4) output projection
    {
        dim3 grid(DIMS / BN, SEQ / BM);
        gemm_tn_bias<<<grid, 256>>>(attn_ptr, out_w, out_b, outp, SEQ, DIMS, DIMS);
    }
}